// round 10
// baseline (speedup 1.0000x reference)
#include <cuda_runtime.h>
#include <cuda_bf16.h>
#include <cstdint>

#define NROWS 100000
#define DIN   128
#define DH    256
#define DOUT  128
#define KNEI  16
#define EPSBN 1e-5f
#define SLOPE 0.2f

// ---------------- device scratch (no allocations allowed) ------------------------
__device__ float g_y1[(size_t)NROWS * DH];   // layer1 out fp32
__device__ float g_y2[(size_t)NROWS * DH];   // layer2 out fp32
__device__ float g_W2e[DH * DH];             // folded W2 (fp32)
__device__ float g_b2e[DH];
__device__ float g_W3e[DOUT * DH];           // folded W3 (fp32)
__device__ float g_b3e[DOUT];
__device__ float g_sum1[DH], g_sq1[DH];
__device__ float g_sum2[DH], g_sq2[DH];
__device__ float g_sum3[DOUT], g_sq3[DOUT];
__device__ float g_a3[DOUT], g_c3[DOUT];

// ---------------- helpers ---------------------------------------------------------
__device__ __forceinline__ uint32_t smem_u32(const void* p) {
    uint32_t a;
    asm("{ .reg .u64 t; cvta.to.shared.u64 t, %1; cvt.u32.u64 %0, t; }" : "=r"(a) : "l"(p));
    return a;
}
__device__ __forceinline__ void ldsm4(uint32_t* d, uint32_t addr) {
    asm volatile("ldmatrix.sync.aligned.m8n8.x4.shared.b16 {%0,%1,%2,%3}, [%4];"
                 : "=r"(d[0]), "=r"(d[1]), "=r"(d[2]), "=r"(d[3]) : "r"(addr));
}
__device__ __forceinline__ void mma16816(float* c, const uint32_t* a, const uint32_t* b) {
    asm volatile("mma.sync.aligned.m16n8k16.row.col.f32.bf16.bf16.f32 "
                 "{%0,%1,%2,%3}, {%4,%5,%6,%7}, {%8,%9}, {%0,%1,%2,%3};"
                 : "+f"(c[0]), "+f"(c[1]), "+f"(c[2]), "+f"(c[3])
                 : "r"(a[0]), "r"(a[1]), "r"(a[2]), "r"(a[3]), "r"(b[0]), "r"(b[1]));
}
__device__ __forceinline__ uint32_t pack_bf2(float x, float y) {
    __nv_bfloat16 a = __float2bfloat16(x), b = __float2bfloat16(y);
    return (uint32_t)__bfloat16_as_ushort(a) | ((uint32_t)__bfloat16_as_ushort(b) << 16);
}
__device__ __forceinline__ void split2(float x, float y, uint32_t& hw, uint32_t& lw) {
    __nv_bfloat16 a = __float2bfloat16(x), b = __float2bfloat16(y);
    hw = (uint32_t)__bfloat16_as_ushort(a) | ((uint32_t)__bfloat16_as_ushort(b) << 16);
    lw = pack_bf2(x - __bfloat162float(a), y - __bfloat162float(b));
}

// ---------------- smem geometry (natural padded layout, ARS=80 proven) -----------
// BM=64, BN=NO (full width), BK=32 bf16.  256 threads, 8 warps: 2m x 4n,
// warp tile 32m x (NO/4)n.  Double-buffered stages.  2 CTAs/SM.
#define ARS   80

// ---------------- tile loaders (fp32 sources, split to bf16 hi/lo inline) --------
template <int KD>
__device__ __forceinline__ void ldgA(float4 v[2], const float* __restrict__ A,
                                     int bm0, int kb, int tid) {
    int r = tid >> 2;                      // 0..63
    int gr = bm0 + r;
    const float* p = A + (size_t)gr * KD + kb * 32 + (tid & 3) * 8;
    bool ok = gr < NROWS;
    v[0] = ok ? __ldg((const float4*)(p))     : make_float4(0.f, 0.f, 0.f, 0.f);
    v[1] = ok ? __ldg((const float4*)(p + 4)) : make_float4(0.f, 0.f, 0.f, 0.f);
}

__device__ __forceinline__ void stsA(char* aH, char* aL, const float4 v[2], int tid) {
    int r = tid >> 2;
    int e = (tid & 3) * 16;
#pragma unroll
    for (int i = 0; i < 2; i++) {
        float4 f = v[i];
        uint32_t h0, l0, h1, l1;
        split2(f.x, f.y, h0, l0);
        split2(f.z, f.w, h1, l1);
        int off = r * ARS + e + i * 8;
        *(uint2*)(aH + off) = make_uint2(h0, h1);
        *(uint2*)(aL + off) = make_uint2(l0, l1);
    }
}

template <int KD, int NO>
__device__ __forceinline__ void ldgB(float4 v[NO / 32], const float* __restrict__ W,
                                     int kb, int tid) {
    if (NO == 256) {
        const float* p = W + (size_t)tid * KD + kb * 32;
#pragma unroll
        for (int i = 0; i < NO / 32; i++) v[i] = __ldg((const float4*)(p + i * 4));
    } else {
        int r = tid >> 1;
        const float* p = W + (size_t)r * KD + kb * 32 + (tid & 1) * 16;
#pragma unroll
        for (int i = 0; i < NO / 32; i++) v[i] = __ldg((const float4*)(p + i * 4));
    }
}

template <int NO>
__device__ __forceinline__ void stsB(char* bH, char* bL, const float4 v[NO / 32], int tid) {
    if (NO == 256) {
#pragma unroll
        for (int i = 0; i < NO / 32; i++) {
            float4 f = v[i];
            uint32_t h0, l0, h1, l1;
            split2(f.x, f.y, h0, l0);
            split2(f.z, f.w, h1, l1);
            int off = tid * ARS + i * 8;
            *(uint2*)(bH + off) = make_uint2(h0, h1);
            *(uint2*)(bL + off) = make_uint2(l0, l1);
        }
    } else {
        int r = tid >> 1;
        int e = (tid & 1) * 32;
#pragma unroll
        for (int i = 0; i < NO / 32; i++) {
            float4 f = v[i];
            uint32_t h0, l0, h1, l1;
            split2(f.x, f.y, h0, l0);
            split2(f.z, f.w, h1, l1);
            int off = r * ARS + e + i * 8;
            *(uint2*)(bH + off) = make_uint2(h0, h1);
            *(uint2*)(bL + off) = make_uint2(l0, l1);
        }
    }
}

// ---------------- compute one BK=32 stage (ldmatrix fragments, bf16x3) -----------
// MT=2 m-tiles of 16 (warp 32 rows), NT n-tiles of 8.
// B fragments loaded per n-pair and consumed immediately (low liveness).
template <int NT>
__device__ __forceinline__ void computeStage(uint32_t sAh, uint32_t sAl,
                                             uint32_t sBh, uint32_t sBl,
                                             float acc[2][NT][4], int wid, int lane) {
    const int mbase = (wid >> 2) * 32;
    const int nbase = (wid & 3) * (NT * 8);
    const int q = lane >> 3, rr = lane & 7;
#pragma unroll
    for (int ks = 0; ks < 2; ks++) {
        uint32_t ah[2][4], al[2][4];
#pragma unroll
        for (int mt = 0; mt < 2; mt++) {
            uint32_t arow = (uint32_t)(mbase + mt * 16 + ((q & 1) << 3) + rr);
            uint32_t aaddr = arow * ARS + (uint32_t)(ks * 32 + (q >> 1) * 16);
            ldsm4(ah[mt], sAh + aaddr);
            ldsm4(al[mt], sAl + aaddr);
        }
#pragma unroll
        for (int p = 0; p < NT / 2; p++) {
            uint32_t brow = (uint32_t)(nbase + p * 16 + ((q >> 1) << 3) + rr);
            uint32_t baddr = brow * ARS + (uint32_t)(ks * 32 + (q & 1) * 16);
            uint32_t bh[4], bl[4];
            ldsm4(bh, sBh + baddr);
            ldsm4(bl, sBl + baddr);
#pragma unroll
            for (int mt = 0; mt < 2; mt++) {
#pragma unroll
                for (int j = 0; j < 2; j++) {
                    int nt = 2 * p + j;
                    uint32_t b0h[2] = {bh[j * 2], bh[j * 2 + 1]};
                    uint32_t b0l[2] = {bl[j * 2], bl[j * 2 + 1]};
                    mma16816(acc[mt][nt], ah[mt], b0h);
                    mma16816(acc[mt][nt], al[mt], b0h);
                    mma16816(acc[mt][nt], ah[mt], b0l);
                }
            }
        }
    }
}

// ---------------- GEMM kernel: Y = LeakyReLU(A @ W^T + bias), + col stats --------
template <int KD, int NO, int MODE>
__global__ void __launch_bounds__(256, 2)
gemm_mma3(const float* __restrict__ Xext, const float* __restrict__ bext,
          float* __restrict__ Yext) {
    extern __shared__ char smem[];
    constexpr int NKB = KD / 32;
    constexpr int NT = NO / 32;                 // n-tiles of 8 per warp
    constexpr int AHO = 0, ALO = 5120, BHO = 10240;
    constexpr int BLO = BHO + NO * ARS;
    constexpr int STG = BHO + 2 * NO * ARS;     // bytes per stage
    constexpr int OEPI = 2 * STG;
    const int tid = threadIdx.x, wid = tid >> 5, lane = tid & 31;
    const int bm0 = blockIdx.x * 64;
    const uint32_t sb = smem_u32(smem);

    const float* A = (MODE == 0) ? Xext : (MODE == 1 ? g_y1 : g_y2);
    const float* Wp = (MODE == 1) ? g_W2e : g_W3e;
    const float* bias = (MODE == 0) ? bext : (MODE == 1 ? g_b2e : g_b3e);
    float* Y    = (MODE == 0) ? g_y1 : (MODE == 1 ? g_y2 : Yext);
    float* gsum = (MODE == 0) ? g_sum1 : (MODE == 1 ? g_sum2 : g_sum3);
    float* gsq  = (MODE == 0) ? g_sq1  : (MODE == 1 ? g_sq2  : g_sq3);
    // For MODE 0, Yext carries W1 (unused as an output there).
    const float* Wsel = (MODE == 0) ? Yext : Wp;

    float* s_bias = (float*)(smem + OEPI);
    float* s_sum  = s_bias + NO;
    float* s_sq   = s_sum + NO;
    if (tid < NO) { s_bias[tid] = __ldg(bias + tid); s_sum[tid] = 0.f; s_sq[tid] = 0.f; }

    float acc[2][NT][4];
#pragma unroll
    for (int i = 0; i < 2; i++)
#pragma unroll
        for (int j = 0; j < NT; j++)
#pragma unroll
            for (int k = 0; k < 4; k++) acc[i][j][k] = 0.f;

    float4 va[2], vb[NO / 32];
    // prologue: stage 0 -> buf0, prefetch stage 1 into regs
    ldgA<KD>(va, A, bm0, 0, tid);
    ldgB<KD, NO>(vb, Wsel, 0, tid);
    stsA(smem + AHO, smem + ALO, va, tid);
    stsB<NO>(smem + BHO, smem + BLO, vb, tid);
    if (NKB > 1) {
        ldgA<KD>(va, A, bm0, 1, tid);
        ldgB<KD, NO>(vb, Wsel, 1, tid);
    }
    __syncthreads();

#pragma unroll
    for (int kb = 0; kb < NKB; kb++) {
        const int cur = (kb & 1) * STG;
        const int nxt = ((kb + 1) & 1) * STG;
        if (kb + 1 < NKB) {                 // store stage kb+1 (other buffer)
            stsA(smem + nxt + AHO, smem + nxt + ALO, va, tid);
            stsB<NO>(smem + nxt + BHO, smem + nxt + BLO, vb, tid);
        }
        if (kb + 2 < NKB) {                 // prefetch stage kb+2 into regs
            ldgA<KD>(va, A, bm0, kb + 2, tid);
            ldgB<KD, NO>(vb, Wsel, kb + 2, tid);
        }
        computeStage<NT>(sb + cur + AHO, sb + cur + ALO, sb + cur + BHO, sb + cur + BLO,
                         acc, wid, lane);
        __syncthreads();
    }

    // epilogue: bias + leaky + store + stats
    const int mbase = (wid >> 2) * 32;
    const int wn = (wid & 3) * (NT * 8);
    float csum[NT][2], csq[NT][2];
#pragma unroll
    for (int nt = 0; nt < NT; nt++) { csum[nt][0] = csum[nt][1] = 0.f; csq[nt][0] = csq[nt][1] = 0.f; }

#pragma unroll
    for (int mt = 0; mt < 2; mt++) {
        int r0 = bm0 + mbase + mt * 16 + (lane >> 2);
        int r1 = r0 + 8;
#pragma unroll
        for (int nt = 0; nt < NT; nt++) {
            int jl = wn + nt * 8 + (lane & 3) * 2;
            float b0 = s_bias[jl], b1 = s_bias[jl + 1];
            float x0 = acc[mt][nt][0] + b0; x0 = x0 > 0.f ? x0 : SLOPE * x0;
            float x1 = acc[mt][nt][1] + b1; x1 = x1 > 0.f ? x1 : SLOPE * x1;
            float x2 = acc[mt][nt][2] + b0; x2 = x2 > 0.f ? x2 : SLOPE * x2;
            float x3 = acc[mt][nt][3] + b1; x3 = x3 > 0.f ? x3 : SLOPE * x3;
            if (r0 < NROWS) {
                *(float2*)(Y + (size_t)r0 * NO + jl) = make_float2(x0, x1);
                csum[nt][0] += x0; csum[nt][1] += x1;
                csq[nt][0] += x0 * x0; csq[nt][1] += x1 * x1;
            }
            if (r1 < NROWS) {
                *(float2*)(Y + (size_t)r1 * NO + jl) = make_float2(x2, x3);
                csum[nt][0] += x2; csum[nt][1] += x3;
                csq[nt][0] += x2 * x2; csq[nt][1] += x3 * x3;
            }
        }
    }
#pragma unroll
    for (int nt = 0; nt < NT; nt++)
#pragma unroll
        for (int p = 0; p < 2; p++) {
            float s = csum[nt][p], q = csq[nt][p];
            s += __shfl_xor_sync(0xFFFFFFFFu, s, 4);  q += __shfl_xor_sync(0xFFFFFFFFu, q, 4);
            s += __shfl_xor_sync(0xFFFFFFFFu, s, 8);  q += __shfl_xor_sync(0xFFFFFFFFu, q, 8);
            s += __shfl_xor_sync(0xFFFFFFFFu, s, 16); q += __shfl_xor_sync(0xFFFFFFFFu, q, 16);
            if (lane < 4) {
                int col = wn + nt * 8 + lane * 2 + p;
                atomicAdd(&s_sum[col], s);
                atomicAdd(&s_sq[col], q);
            }
        }
    __syncthreads();
    if (tid < NO) {
        atomicAdd(gsum + tid, s_sum[tid]);
        atomicAdd(gsq + tid, s_sq[tid]);
    }
}

// ---------------- R5-verbatim small kernels --------------------------------------
__global__ void zero_stats_kernel() {
    int t = threadIdx.x;  // 256
    g_sum1[t] = 0.f; g_sq1[t] = 0.f;
    g_sum2[t] = 0.f; g_sq2[t] = 0.f;
    if (t < DOUT) { g_sum3[t] = 0.f; g_sq3[t] = 0.f; }
}

__global__ void fold_kernel(const float* __restrict__ W, const float* __restrict__ b,
                            const float* __restrict__ g, const float* __restrict__ beta,
                            int layer) {
    int j = threadIdx.x;   // 256 = DH
    int o = blockIdx.x;
    const float* sum = (layer == 1) ? g_sum1 : g_sum2;
    const float* sq  = (layer == 1) ? g_sq1  : g_sq2;
    float* We        = (layer == 1) ? g_W2e  : g_W3e;
    float* be        = (layer == 1) ? g_b2e  : g_b3e;

    const float invN = 1.0f / (float)NROWS;
    float mean = sum[j] * invN;
    float var  = sq[j] * invN - mean * mean;
    float a = g[j] * rsqrtf(var + EPSBN);
    float c = beta[j] - mean * a;
    float w = W[o * DH + j];
    We[o * DH + j] = w * a;

    __shared__ float red[DH];
    red[j] = w * c;
    __syncthreads();
    for (int s = DH / 2; s > 0; s >>= 1) {
        if (j < s) red[j] += red[j + s];
        __syncthreads();
    }
    if (j == 0) be[o] = b[o] + red[0];
}

__global__ void prep3_kernel(const float* __restrict__ g, const float* __restrict__ beta) {
    int j = threadIdx.x;  // 128
    const float invN = 1.0f / (float)NROWS;
    float mean = g_sum3[j] * invN;
    float var  = g_sq3[j] * invN - mean * mean;
    float a = g[j] * rsqrtf(var + EPSBN);
    g_a3[j] = a;
    g_c3[j] = beta[j] - mean * a;
}

__global__ void affine_kernel(float* __restrict__ f) {
    long long idx = (long long)blockIdx.x * blockDim.x + threadIdx.x;
    if (idx * 4 >= (long long)NROWS * DOUT) return;
    float4 v = *(float4*)(f + idx * 4);
    int j = (int)((idx * 4) & (DOUT - 1));
    v.x = v.x * g_a3[j]     + g_c3[j];
    v.y = v.y * g_a3[j + 1] + g_c3[j + 1];
    v.z = v.z * g_a3[j + 2] + g_c3[j + 2];
    v.w = v.w * g_a3[j + 3] + g_c3[j + 3];
    *(float4*)(f + idx * 4) = v;
}

__global__ void gather_kernel(const int* __restrict__ nidx, const float* __restrict__ f,
                              float* __restrict__ out) {
    __shared__ int sidx[2 * KNEI];
    int tid = threadIdx.x;              // 256 threads = 2 nodes
    int node0 = blockIdx.x * 2;
    if (tid < 2 * KNEI) sidx[tid] = nidx[(size_t)node0 * KNEI + tid];
    __syncthreads();
    int local = tid >> 7;
    int j = tid & (DOUT - 1);
    float s = 0.f;
#pragma unroll
    for (int k = 0; k < KNEI; k++) {
        int nk = sidx[local * KNEI + k];
        s += __ldg(f + (size_t)nk * DOUT + j);
    }
    out[(size_t)(node0 + local) * DOUT + j] = s * (1.0f / KNEI);
}

// ---------------------------------------------------------------------------------
extern "C" void kernel_launch(void* const* d_in, const int* in_sizes, int n_in,
                              void* d_out, int out_size) {
    const float* X   = (const float*)d_in[0];
    const int*   nid = (const int*)d_in[1];
    const float* W1  = (const float*)d_in[3];
    const float* b1  = (const float*)d_in[4];
    const float* g1  = (const float*)d_in[5];
    const float* be1 = (const float*)d_in[6];
    const float* W2  = (const float*)d_in[7];
    const float* b2  = (const float*)d_in[8];
    const float* g2  = (const float*)d_in[9];
    const float* be2 = (const float*)d_in[10];
    const float* W3  = (const float*)d_in[11];
    const float* b3  = (const float*)d_in[12];
    const float* g3  = (const float*)d_in[13];
    const float* be3 = (const float*)d_in[14];

    float* out  = (float*)d_out;                   // node_update [N, DOUT]
    float* fbuf = out + (size_t)NROWS * DOUT;      // f           [N, DOUT]

    const int mblocks = (NROWS + 63) / 64;         // 1563
    const int SM256 = 2 * (10240 + 2 * 256 * ARS) + 3 * 256 * 4;   // 105472
    const int SM128 = 2 * (10240 + 2 * 128 * ARS) + 3 * 128 * 4;   // 63488

    cudaFuncSetAttribute(gemm_mma3<128, 256, 0>, cudaFuncAttributeMaxDynamicSharedMemorySize, SM256);
    cudaFuncSetAttribute(gemm_mma3<256, 256, 1>, cudaFuncAttributeMaxDynamicSharedMemorySize, SM256);
    cudaFuncSetAttribute(gemm_mma3<256, 128, 2>, cudaFuncAttributeMaxDynamicSharedMemorySize, SM128);

    zero_stats_kernel<<<1, 256>>>();

    // layer 1: X @ W1^T -> g_y1 (+stats1).  W1 passed via 3rd arg (unused as output in MODE 0)
    gemm_mma3<128, 256, 0><<<mblocks, 256, SM256>>>(X, b1, (float*)W1);
    fold_kernel<<<DH, DH>>>(W2, b2, g1, be1, 1);
    gemm_mma3<256, 256, 1><<<mblocks, 256, SM256>>>(nullptr, nullptr, nullptr);
    fold_kernel<<<DOUT, DH>>>(W3, b3, g2, be2, 2);
    // layer 3: g_y2 @ W3e^T -> fbuf (raw y3, +stats3)
    gemm_mma3<256, 128, 2><<<mblocks, 256, SM128>>>(nullptr, nullptr, fbuf);

    prep3_kernel<<<1, DOUT>>>(g3, be3);
    affine_kernel<<<(NROWS * DOUT / 4 + 255) / 256, 256>>>(fbuf);
    gather_kernel<<<NROWS / 2, 256>>>(nid, fbuf, out);
}

// round 11
// speedup vs baseline: 1.0065x; 1.0065x over previous
#include <cuda_runtime.h>
#include <cuda_bf16.h>
#include <cstdint>

#define NROWS 100000
#define DIN   128
#define DH    256
#define DOUT  128
#define KNEI  16
#define EPSBN 1e-5f
#define SLOPE 0.2f

// ---------------- device scratch (no allocations allowed) ------------------------
__device__ float g_y1[(size_t)NROWS * DH];   // layer1 out fp32
__device__ float g_y2[(size_t)NROWS * DH];   // layer2 out fp32
__device__ float g_W2e[DH * DH];             // folded W2 (fp32)
__device__ float g_b2e[DH];
__device__ float g_W3e[DOUT * DH];           // folded W3 (fp32)
__device__ float g_b3e[DOUT];
__device__ float g_sum1[DH], g_sq1[DH];
__device__ float g_sum2[DH], g_sq2[DH];
__device__ float g_sum3[DOUT], g_sq3[DOUT];
__device__ float g_a3[DOUT], g_c3[DOUT];

// ---------------- helpers ---------------------------------------------------------
__device__ __forceinline__ uint32_t smem_u32(const void* p) {
    uint32_t a;
    asm("{ .reg .u64 t; cvta.to.shared.u64 t, %1; cvt.u32.u64 %0, t; }" : "=r"(a) : "l"(p));
    return a;
}
__device__ __forceinline__ void ldsm4(uint32_t* d, uint32_t addr) {
    asm volatile("ldmatrix.sync.aligned.m8n8.x4.shared.b16 {%0,%1,%2,%3}, [%4];"
                 : "=r"(d[0]), "=r"(d[1]), "=r"(d[2]), "=r"(d[3]) : "r"(addr));
}
__device__ __forceinline__ void mma16816(float* c, const uint32_t* a, const uint32_t* b) {
    asm volatile("mma.sync.aligned.m16n8k16.row.col.f32.bf16.bf16.f32 "
                 "{%0,%1,%2,%3}, {%4,%5,%6,%7}, {%8,%9}, {%0,%1,%2,%3};"
                 : "+f"(c[0]), "+f"(c[1]), "+f"(c[2]), "+f"(c[3])
                 : "r"(a[0]), "r"(a[1]), "r"(a[2]), "r"(a[3]), "r"(b[0]), "r"(b[1]));
}
__device__ __forceinline__ uint32_t pack_bf2(float x, float y) {
    __nv_bfloat16 a = __float2bfloat16(x), b = __float2bfloat16(y);
    return (uint32_t)__bfloat16_as_ushort(a) | ((uint32_t)__bfloat16_as_ushort(b) << 16);
}
__device__ __forceinline__ void split2(float x, float y, uint32_t& hw, uint32_t& lw) {
    __nv_bfloat16 a = __float2bfloat16(x), b = __float2bfloat16(y);
    hw = (uint32_t)__bfloat16_as_ushort(a) | ((uint32_t)__bfloat16_as_ushort(b) << 16);
    lw = pack_bf2(x - __bfloat162float(a), y - __bfloat162float(b));
}

// ---------------- smem geometry (natural padded layout, ARS=80 proven) -----------
// BM=64, BN=NO (full width), BK=32 bf16.  128 threads, 4 warps: 1m x 4n,
// warp tile 64m x (NO/4)n.  Single-buffered stage; 2 CTAs/SM for overlap.
#define ARS   80

// ---------------- tile loaders (fp32 sources, split to bf16 hi/lo inline) --------
// A tile: 64 rows x 32 cols fp32; 128 threads, 16 floats each.
template <int KD>
__device__ __forceinline__ void ldgA(float4 v[4], const float* __restrict__ A,
                                     int bm0, int kb, int tid) {
    int r = tid >> 1;                      // 0..63
    int gr = bm0 + r;
    const float* p = A + (size_t)gr * KD + kb * 32 + (tid & 1) * 16;
    bool ok = gr < NROWS;
#pragma unroll
    for (int i = 0; i < 4; i++)
        v[i] = ok ? __ldg((const float4*)(p + i * 4)) : make_float4(0.f, 0.f, 0.f, 0.f);
}

__device__ __forceinline__ void stsA(char* aH, char* aL, const float4 v[4], int tid) {
    int r = tid >> 1;
    int e = (tid & 1) * 32;
#pragma unroll
    for (int i = 0; i < 4; i++) {
        float4 f = v[i];
        uint32_t h0, l0, h1, l1;
        split2(f.x, f.y, h0, l0);
        split2(f.z, f.w, h1, l1);
        int off = r * ARS + e + i * 8;
        *(uint2*)(aH + off) = make_uint2(h0, h1);
        *(uint2*)(aL + off) = make_uint2(l0, l1);
    }
}

// B: direct LDG -> split -> STS (no reg prefetch; weights are L2-resident).
// NO/128 rows per thread, 32 cols each.
template <int KD, int NO>
__device__ __forceinline__ void ldstB(char* bH, char* bL, const float* __restrict__ W,
                                      int kb, int tid) {
#pragma unroll
    for (int rep = 0; rep < NO / 128; rep++) {
        int r = tid + rep * 128;
        const float* p = W + (size_t)r * KD + kb * 32;
        float4 v[8];
#pragma unroll
        for (int i = 0; i < 8; i++) v[i] = __ldg((const float4*)(p + i * 4));
#pragma unroll
        for (int i = 0; i < 8; i++) {
            float4 f = v[i];
            uint32_t h0, l0, h1, l1;
            split2(f.x, f.y, h0, l0);
            split2(f.z, f.w, h1, l1);
            int off = r * ARS + i * 8;
            *(uint2*)(bH + off) = make_uint2(h0, h1);
            *(uint2*)(bL + off) = make_uint2(l0, l1);
        }
    }
}

// ---------------- compute one BK=32 stage (ldmatrix fragments, bf16x3) -----------
// 4 warps all in n: warp tile 64m x (NT*8)n.  MT=4 m-tiles of 16.
template <int NT>
__device__ __forceinline__ void computeStage(uint32_t sAh, uint32_t sAl,
                                             uint32_t sBh, uint32_t sBl,
                                             float acc[4][NT][4], int wid, int lane) {
    const int nbase = wid * (NT * 8);
    const int q = lane >> 3, rr = lane & 7;
#pragma unroll
    for (int ks = 0; ks < 2; ks++) {
        uint32_t bh[NT / 2][4], bl[NT / 2][4];
#pragma unroll
        for (int p = 0; p < NT / 2; p++) {
            uint32_t brow = (uint32_t)(nbase + p * 16 + ((q >> 1) << 3) + rr);
            uint32_t baddr = brow * ARS + (uint32_t)(ks * 32 + (q & 1) * 16);
            ldsm4(bh[p], sBh + baddr);
            ldsm4(bl[p], sBl + baddr);
        }
#pragma unroll
        for (int mt = 0; mt < 4; mt++) {
            uint32_t arow = (uint32_t)(mt * 16 + ((q & 1) << 3) + rr);
            uint32_t aaddr = arow * ARS + (uint32_t)(ks * 32 + (q >> 1) * 16);
            uint32_t ah[4], al[4];
            ldsm4(ah, sAh + aaddr);
            ldsm4(al, sAl + aaddr);
#pragma unroll
            for (int nt = 0; nt < NT; nt++) {
                uint32_t b0h[2] = {bh[nt >> 1][(nt & 1) * 2], bh[nt >> 1][(nt & 1) * 2 + 1]};
                uint32_t b0l[2] = {bl[nt >> 1][(nt & 1) * 2], bl[nt >> 1][(nt & 1) * 2 + 1]};
                mma16816(acc[mt][nt], ah, b0h);
                mma16816(acc[mt][nt], al, b0h);
                mma16816(acc[mt][nt], ah, b0l);
            }
        }
    }
}

// ---------------- GEMM kernel: Y = LeakyReLU(A @ W^T + bias), + col stats --------
template <int KD, int NO, int MODE>
__global__ void __launch_bounds__(128, 2)
gemm_mma3(const float* __restrict__ Xext, const float* __restrict__ bext,
          float* __restrict__ Yext) {
    extern __shared__ char smem[];
    constexpr int NKB = KD / 32;
    constexpr int NT = NO / 32;                 // n-tiles of 8 per warp
    constexpr int AHO = 0, ALO = 5120, BHO = 10240;
    constexpr int BLO = BHO + NO * ARS;
    constexpr int OEPI = BHO + 2 * NO * ARS;
    const int tid = threadIdx.x, wid = tid >> 5, lane = tid & 31;
    const int bm0 = blockIdx.x * 64;
    const uint32_t sb = smem_u32(smem);

    const float* A = (MODE == 0) ? Xext : (MODE == 1 ? g_y1 : g_y2);
    const float* Wp = (MODE == 1) ? g_W2e : g_W3e;
    const float* bias = (MODE == 0) ? bext : (MODE == 1 ? g_b2e : g_b3e);
    float* Y    = (MODE == 0) ? g_y1 : (MODE == 1 ? g_y2 : Yext);
    float* gsum = (MODE == 0) ? g_sum1 : (MODE == 1 ? g_sum2 : g_sum3);
    float* gsq  = (MODE == 0) ? g_sq1  : (MODE == 1 ? g_sq2  : g_sq3);
    // For MODE 0, Yext carries W1 (unused as an output there).
    const float* Wsel = (MODE == 0) ? Yext : Wp;

    float* s_bias = (float*)(smem + OEPI);
    float* s_sum  = s_bias + NO;
    float* s_sq   = s_sum + NO;
    for (int c = tid; c < NO; c += 128) {
        s_bias[c] = __ldg(bias + c);
        s_sum[c] = 0.f;
        s_sq[c] = 0.f;
    }

    float acc[4][NT][4];
#pragma unroll
    for (int i = 0; i < 4; i++)
#pragma unroll
        for (int j = 0; j < NT; j++)
#pragma unroll
            for (int k = 0; k < 4; k++) acc[i][j][k] = 0.f;

    float4 va[4];
    ldgA<KD>(va, A, bm0, 0, tid);

#pragma unroll
    for (int kb = 0; kb < NKB; kb++) {
        __syncthreads();                       // previous compute done
        stsA(smem + AHO, smem + ALO, va, tid);
        ldstB<KD, NO>(smem + BHO, smem + BLO, Wsel, kb, tid);
        __syncthreads();
        if (kb + 1 < NKB) ldgA<KD>(va, A, bm0, kb + 1, tid);  // overlap w/ compute
        computeStage<NT>(sb + AHO, sb + ALO, sb + BHO, sb + BLO, acc, wid, lane);
    }

    // epilogue: bias + leaky + store + stats
    const int wn = wid * (NT * 8);
    float csum[NT][2], csq[NT][2];
#pragma unroll
    for (int nt = 0; nt < NT; nt++) { csum[nt][0] = csum[nt][1] = 0.f; csq[nt][0] = csq[nt][1] = 0.f; }

#pragma unroll
    for (int mt = 0; mt < 4; mt++) {
        int r0 = bm0 + mt * 16 + (lane >> 2);
        int r1 = r0 + 8;
#pragma unroll
        for (int nt = 0; nt < NT; nt++) {
            int jl = wn + nt * 8 + (lane & 3) * 2;
            float b0 = s_bias[jl], b1 = s_bias[jl + 1];
            float x0 = acc[mt][nt][0] + b0; x0 = x0 > 0.f ? x0 : SLOPE * x0;
            float x1 = acc[mt][nt][1] + b1; x1 = x1 > 0.f ? x1 : SLOPE * x1;
            float x2 = acc[mt][nt][2] + b0; x2 = x2 > 0.f ? x2 : SLOPE * x2;
            float x3 = acc[mt][nt][3] + b1; x3 = x3 > 0.f ? x3 : SLOPE * x3;
            if (r0 < NROWS) {
                *(float2*)(Y + (size_t)r0 * NO + jl) = make_float2(x0, x1);
                csum[nt][0] += x0; csum[nt][1] += x1;
                csq[nt][0] += x0 * x0; csq[nt][1] += x1 * x1;
            }
            if (r1 < NROWS) {
                *(float2*)(Y + (size_t)r1 * NO + jl) = make_float2(x2, x3);
                csum[nt][0] += x2; csum[nt][1] += x3;
                csq[nt][0] += x2 * x2; csq[nt][1] += x3 * x3;
            }
        }
    }
#pragma unroll
    for (int nt = 0; nt < NT; nt++)
#pragma unroll
        for (int p = 0; p < 2; p++) {
            float s = csum[nt][p], q = csq[nt][p];
            s += __shfl_xor_sync(0xFFFFFFFFu, s, 4);  q += __shfl_xor_sync(0xFFFFFFFFu, q, 4);
            s += __shfl_xor_sync(0xFFFFFFFFu, s, 8);  q += __shfl_xor_sync(0xFFFFFFFFu, q, 8);
            s += __shfl_xor_sync(0xFFFFFFFFu, s, 16); q += __shfl_xor_sync(0xFFFFFFFFu, q, 16);
            if (lane < 4) {
                int col = wn + nt * 8 + lane * 2 + p;
                atomicAdd(&s_sum[col], s);
                atomicAdd(&s_sq[col], q);
            }
        }
    __syncthreads();
    for (int c = tid; c < NO; c += 128) {
        atomicAdd(gsum + c, s_sum[c]);
        atomicAdd(gsq + c, s_sq[c]);
    }
}

// ---------------- R5-verbatim small kernels --------------------------------------
__global__ void zero_stats_kernel() {
    int t = threadIdx.x;  // 256
    g_sum1[t] = 0.f; g_sq1[t] = 0.f;
    g_sum2[t] = 0.f; g_sq2[t] = 0.f;
    if (t < DOUT) { g_sum3[t] = 0.f; g_sq3[t] = 0.f; }
}

__global__ void fold_kernel(const float* __restrict__ W, const float* __restrict__ b,
                            const float* __restrict__ g, const float* __restrict__ beta,
                            int layer) {
    int j = threadIdx.x;   // 256 = DH
    int o = blockIdx.x;
    const float* sum = (layer == 1) ? g_sum1 : g_sum2;
    const float* sq  = (layer == 1) ? g_sq1  : g_sq2;
    float* We        = (layer == 1) ? g_W2e  : g_W3e;
    float* be        = (layer == 1) ? g_b2e  : g_b3e;

    const float invN = 1.0f / (float)NROWS;
    float mean = sum[j] * invN;
    float var  = sq[j] * invN - mean * mean;
    float a = g[j] * rsqrtf(var + EPSBN);
    float c = beta[j] - mean * a;
    float w = W[o * DH + j];
    We[o * DH + j] = w * a;

    __shared__ float red[DH];
    red[j] = w * c;
    __syncthreads();
    for (int s = DH / 2; s > 0; s >>= 1) {
        if (j < s) red[j] += red[j + s];
        __syncthreads();
    }
    if (j == 0) be[o] = b[o] + red[0];
}

__global__ void prep3_kernel(const float* __restrict__ g, const float* __restrict__ beta) {
    int j = threadIdx.x;  // 128
    const float invN = 1.0f / (float)NROWS;
    float mean = g_sum3[j] * invN;
    float var  = g_sq3[j] * invN - mean * mean;
    float a = g[j] * rsqrtf(var + EPSBN);
    g_a3[j] = a;
    g_c3[j] = beta[j] - mean * a;
}

__global__ void affine_kernel(float* __restrict__ f) {
    long long idx = (long long)blockIdx.x * blockDim.x + threadIdx.x;
    if (idx * 4 >= (long long)NROWS * DOUT) return;
    float4 v = *(float4*)(f + idx * 4);
    int j = (int)((idx * 4) & (DOUT - 1));
    v.x = v.x * g_a3[j]     + g_c3[j];
    v.y = v.y * g_a3[j + 1] + g_c3[j + 1];
    v.z = v.z * g_a3[j + 2] + g_c3[j + 2];
    v.w = v.w * g_a3[j + 3] + g_c3[j + 3];
    *(float4*)(f + idx * 4) = v;
}

__global__ void gather_kernel(const int* __restrict__ nidx, const float* __restrict__ f,
                              float* __restrict__ out) {
    __shared__ int sidx[2 * KNEI];
    int tid = threadIdx.x;              // 256 threads = 2 nodes
    int node0 = blockIdx.x * 2;
    if (tid < 2 * KNEI) sidx[tid] = nidx[(size_t)node0 * KNEI + tid];
    __syncthreads();
    int local = tid >> 7;
    int j = tid & (DOUT - 1);
    float s = 0.f;
#pragma unroll
    for (int k = 0; k < KNEI; k++) {
        int nk = sidx[local * KNEI + k];
        s += __ldg(f + (size_t)nk * DOUT + j);
    }
    out[(size_t)(node0 + local) * DOUT + j] = s * (1.0f / KNEI);
}

// ---------------------------------------------------------------------------------
extern "C" void kernel_launch(void* const* d_in, const int* in_sizes, int n_in,
                              void* d_out, int out_size) {
    const float* X   = (const float*)d_in[0];
    const int*   nid = (const int*)d_in[1];
    const float* W1  = (const float*)d_in[3];
    const float* b1  = (const float*)d_in[4];
    const float* g1  = (const float*)d_in[5];
    const float* be1 = (const float*)d_in[6];
    const float* W2  = (const float*)d_in[7];
    const float* b2  = (const float*)d_in[8];
    const float* g2  = (const float*)d_in[9];
    const float* be2 = (const float*)d_in[10];
    const float* W3  = (const float*)d_in[11];
    const float* b3  = (const float*)d_in[12];
    const float* g3  = (const float*)d_in[13];
    const float* be3 = (const float*)d_in[14];

    float* out  = (float*)d_out;                   // node_update [N, DOUT]
    float* fbuf = out + (size_t)NROWS * DOUT;      // f           [N, DOUT]

    const int mblocks = (NROWS + 63) / 64;         // 1563
    const int SM256 = 10240 + 2 * 256 * ARS + 3 * 256 * 4;   // 54272
    const int SM128 = 10240 + 2 * 128 * ARS + 3 * 128 * 4;   // 32256

    cudaFuncSetAttribute(gemm_mma3<128, 256, 0>, cudaFuncAttributeMaxDynamicSharedMemorySize, SM256);
    cudaFuncSetAttribute(gemm_mma3<256, 256, 1>, cudaFuncAttributeMaxDynamicSharedMemorySize, SM256);
    cudaFuncSetAttribute(gemm_mma3<256, 128, 2>, cudaFuncAttributeMaxDynamicSharedMemorySize, SM128);

    zero_stats_kernel<<<1, 256>>>();

    // layer 1: X @ W1^T -> g_y1 (+stats1).  W1 passed via 3rd arg (unused as output in MODE 0)
    gemm_mma3<128, 256, 0><<<mblocks, 128, SM256>>>(X, b1, (float*)W1);
    fold_kernel<<<DH, DH>>>(W2, b2, g1, be1, 1);
    gemm_mma3<256, 256, 1><<<mblocks, 128, SM256>>>(nullptr, nullptr, nullptr);
    fold_kernel<<<DOUT, DH>>>(W3, b3, g2, be2, 2);
    // layer 3: g_y2 @ W3e^T -> fbuf (raw y3, +stats3)
    gemm_mma3<256, 128, 2><<<mblocks, 128, SM128>>>(nullptr, nullptr, fbuf);

    prep3_kernel<<<1, DOUT>>>(g3, be3);
    affine_kernel<<<(NROWS * DOUT / 4 + 255) / 256, 256>>>(fbuf);
    gather_kernel<<<NROWS / 2, 256>>>(nid, fbuf, out);
}

// round 13
// speedup vs baseline: 1.2286x; 1.2207x over previous
#include <cuda_runtime.h>
#include <cuda_bf16.h>
#include <cstdint>

#define NROWS 100000
#define DIN   128
#define DH    256
#define DOUT  128
#define KNEI  16
#define EPSBN 1e-5f
#define SLOPE 0.2f

// ---------------- device scratch (no allocations allowed) ------------------------
__device__ float g_y1[(size_t)NROWS * DH];   // layer1 out fp32; reused for raw y3
__device__ float g_y2[(size_t)NROWS * DH];   // layer2 out fp32
__device__ float g_W2e[DH * DH];             // folded W2 (fp32)
__device__ float g_b2e[DH];
__device__ float g_W3e[DOUT * DH];           // folded W3 (fp32)
__device__ float g_b3e[DOUT];
__device__ float g_sum1[DH], g_sq1[DH];
__device__ float g_sum2[DH], g_sq2[DH];
__device__ float g_sum3[DOUT], g_sq3[DOUT];
__device__ float g_a3[DOUT], g_c3[DOUT];

// ---------------- helpers ---------------------------------------------------------
__device__ __forceinline__ uint32_t smem_u32(const void* p) {
    uint32_t a;
    asm("{ .reg .u64 t; cvta.to.shared.u64 t, %1; cvt.u32.u64 %0, t; }" : "=r"(a) : "l"(p));
    return a;
}
__device__ __forceinline__ void ldsm4(uint32_t* d, uint32_t addr) {
    asm volatile("ldmatrix.sync.aligned.m8n8.x4.shared.b16 {%0,%1,%2,%3}, [%4];"
                 : "=r"(d[0]), "=r"(d[1]), "=r"(d[2]), "=r"(d[3]) : "r"(addr));
}
__device__ __forceinline__ void mma16816(float* c, const uint32_t* a, const uint32_t* b) {
    asm volatile("mma.sync.aligned.m16n8k16.row.col.f32.bf16.bf16.f32 "
                 "{%0,%1,%2,%3}, {%4,%5,%6,%7}, {%8,%9}, {%0,%1,%2,%3};"
                 : "+f"(c[0]), "+f"(c[1]), "+f"(c[2]), "+f"(c[3])
                 : "r"(a[0]), "r"(a[1]), "r"(a[2]), "r"(a[3]), "r"(b[0]), "r"(b[1]));
}
__device__ __forceinline__ uint32_t pack_bf2(float x, float y) {
    __nv_bfloat16 a = __float2bfloat16(x), b = __float2bfloat16(y);
    return (uint32_t)__bfloat16_as_ushort(a) | ((uint32_t)__bfloat16_as_ushort(b) << 16);
}
__device__ __forceinline__ void split2(float x, float y, uint32_t& hw, uint32_t& lw) {
    __nv_bfloat16 a = __float2bfloat16(x), b = __float2bfloat16(y);
    hw = (uint32_t)__bfloat16_as_ushort(a) | ((uint32_t)__bfloat16_as_ushort(b) << 16);
    lw = pack_bf2(x - __bfloat162float(a), y - __bfloat162float(b));
}

// ---------------- smem geometry (natural padded layout, ARS=80 proven) -----------
// BM=128, BN=NO (full width), BK=32 bf16.  256 threads, 8 warps: 2m x 4n,
// warp tile 64m x (NO/4)n.  Double-buffered stages.  (R8 config, best measured.)
#define ARS   80

// ---------------- tile loaders (fp32 sources, split to bf16 hi/lo inline) --------
template <int KD>
__device__ __forceinline__ void ldgA(float4 v[4], const float* __restrict__ A,
                                     int bm0, int kb, int tid) {
    int r = tid >> 1;                      // 0..127
    int gr = bm0 + r;
    const float* p = A + (size_t)gr * KD + kb * 32 + (tid & 1) * 16;
    bool ok = gr < NROWS;
#pragma unroll
    for (int i = 0; i < 4; i++)
        v[i] = ok ? __ldg((const float4*)(p + i * 4)) : make_float4(0.f, 0.f, 0.f, 0.f);
}

__device__ __forceinline__ void stsA(char* aH, char* aL, const float4 v[4], int tid) {
    int r = tid >> 1;
    int e = (tid & 1) * 32;
#pragma unroll
    for (int i = 0; i < 4; i++) {
        float4 f = v[i];
        uint32_t h0, l0, h1, l1;
        split2(f.x, f.y, h0, l0);
        split2(f.z, f.w, h1, l1);
        int off = r * ARS + e + i * 8;
        *(uint2*)(aH + off) = make_uint2(h0, h1);
        *(uint2*)(aL + off) = make_uint2(l0, l1);
    }
}

template <int KD, int NO>
__device__ __forceinline__ void ldgB(float4 v[NO / 32], const float* __restrict__ W,
                                     int kb, int tid) {
    if (NO == 256) {
        const float* p = W + (size_t)tid * KD + kb * 32;
#pragma unroll
        for (int i = 0; i < NO / 32; i++) v[i] = __ldg((const float4*)(p + i * 4));
    } else {
        int r = tid >> 1;
        const float* p = W + (size_t)r * KD + kb * 32 + (tid & 1) * 16;
#pragma unroll
        for (int i = 0; i < NO / 32; i++) v[i] = __ldg((const float4*)(p + i * 4));
    }
}

template <int NO>
__device__ __forceinline__ void stsB(char* bH, char* bL, const float4 v[NO / 32], int tid) {
    if (NO == 256) {
#pragma unroll
        for (int i = 0; i < NO / 32; i++) {
            float4 f = v[i];
            uint32_t h0, l0, h1, l1;
            split2(f.x, f.y, h0, l0);
            split2(f.z, f.w, h1, l1);
            int off = tid * ARS + i * 8;
            *(uint2*)(bH + off) = make_uint2(h0, h1);
            *(uint2*)(bL + off) = make_uint2(l0, l1);
        }
    } else {
        int r = tid >> 1;
        int e = (tid & 1) * 32;
#pragma unroll
        for (int i = 0; i < NO / 32; i++) {
            float4 f = v[i];
            uint32_t h0, l0, h1, l1;
            split2(f.x, f.y, h0, l0);
            split2(f.z, f.w, h1, l1);
            int off = r * ARS + e + i * 8;
            *(uint2*)(bH + off) = make_uint2(h0, h1);
            *(uint2*)(bL + off) = make_uint2(l0, l1);
        }
    }
}

// ---------------- compute one BK=32 stage (ldmatrix fragments, bf16x3) -----------
template <int NT>
__device__ __forceinline__ void computeStage(uint32_t sAh, uint32_t sAl,
                                             uint32_t sBh, uint32_t sBl,
                                             float acc[4][NT][4], int wid, int lane) {
    const int mbase = (wid >> 2) * 64;
    const int nbase = (wid & 3) * (NT * 8);
    const int q = lane >> 3, rr = lane & 7;
#pragma unroll
    for (int ks = 0; ks < 2; ks++) {
        uint32_t bh[NT / 2][4], bl[NT / 2][4];
#pragma unroll
        for (int p = 0; p < NT / 2; p++) {
            uint32_t brow = (uint32_t)(nbase + p * 16 + ((q >> 1) << 3) + rr);
            uint32_t baddr = brow * ARS + (uint32_t)(ks * 32 + (q & 1) * 16);
            ldsm4(bh[p], sBh + baddr);
            ldsm4(bl[p], sBl + baddr);
        }
#pragma unroll
        for (int mt = 0; mt < 4; mt++) {
            uint32_t arow = (uint32_t)(mbase + mt * 16 + ((q & 1) << 3) + rr);
            uint32_t aaddr = arow * ARS + (uint32_t)(ks * 32 + (q >> 1) * 16);
            uint32_t ah[4], al[4];
            ldsm4(ah, sAh + aaddr);
            ldsm4(al, sAl + aaddr);
#pragma unroll
            for (int nt = 0; nt < NT; nt++) {
                uint32_t b0h[2] = {bh[nt >> 1][(nt & 1) * 2], bh[nt >> 1][(nt & 1) * 2 + 1]};
                uint32_t b0l[2] = {bl[nt >> 1][(nt & 1) * 2], bl[nt >> 1][(nt & 1) * 2 + 1]};
                mma16816(acc[mt][nt], ah, b0h);
                mma16816(acc[mt][nt], al, b0h);
                mma16816(acc[mt][nt], ah, b0l);
            }
        }
    }
}

// ---------------- GEMM kernel: Y = LeakyReLU(A @ W^T + bias), + col stats --------
template <int KD, int NO, int MODE>
__global__ void __launch_bounds__(256, 1)
gemm_mma3(const float* __restrict__ Xext, const float* __restrict__ bext,
          float* __restrict__ Yext) {
    extern __shared__ char smem[];
    constexpr int NKB = KD / 32;
    constexpr int NT = NO / 32;                 // n-tiles of 8 per warp
    constexpr int AHO = 0, ALO = 10240, BHO = 20480;
    constexpr int BLO = BHO + NO * ARS;
    constexpr int STG = BHO + 2 * NO * ARS;     // bytes per stage
    constexpr int OEPI = 2 * STG;
    const int tid = threadIdx.x, wid = tid >> 5, lane = tid & 31;
    const int bm0 = blockIdx.x * 128;
    const uint32_t sb = smem_u32(smem);

    const float* A = (MODE == 0) ? Xext : (MODE == 1 ? g_y1 : g_y2);
    const float* Wp = (MODE == 1) ? g_W2e : g_W3e;
    const float* bias = (MODE == 0) ? bext : (MODE == 1 ? g_b2e : g_b3e);
    float* Y    = (MODE == 0) ? g_y1 : (MODE == 1 ? g_y2 : g_y1);  // MODE 2 -> scratch g_y1
    float* gsum = (MODE == 0) ? g_sum1 : (MODE == 1 ? g_sum2 : g_sum3);
    float* gsq  = (MODE == 0) ? g_sq1  : (MODE == 1 ? g_sq2  : g_sq3);
    // For MODE 0, Yext carries W1 (unused as an output there).
    const float* Wsel = (MODE == 0) ? Yext : Wp;

    float* s_bias = (float*)(smem + OEPI);
    float* s_sum  = s_bias + NO;
    float* s_sq   = s_sum + NO;
    if (tid < NO) { s_bias[tid] = __ldg(bias + tid); s_sum[tid] = 0.f; s_sq[tid] = 0.f; }

    float acc[4][NT][4];
#pragma unroll
    for (int i = 0; i < 4; i++)
#pragma unroll
        for (int j = 0; j < NT; j++)
#pragma unroll
            for (int k = 0; k < 4; k++) acc[i][j][k] = 0.f;

    float4 va[4], vb[NO / 32];
    // prologue: stage 0 -> buf0, prefetch stage 1 into regs
    ldgA<KD>(va, A, bm0, 0, tid);
    ldgB<KD, NO>(vb, Wsel, 0, tid);
    stsA(smem + AHO, smem + ALO, va, tid);
    stsB<NO>(smem + BHO, smem + BLO, vb, tid);
    if (NKB > 1) {
        ldgA<KD>(va, A, bm0, 1, tid);
        ldgB<KD, NO>(vb, Wsel, 1, tid);
    }
    __syncthreads();

#pragma unroll
    for (int kb = 0; kb < NKB; kb++) {
        const int cur = (kb & 1) * STG;
        const int nxt = ((kb + 1) & 1) * STG;
        if (kb + 1 < NKB) {                 // store stage kb+1 (other buffer)
            stsA(smem + nxt + AHO, smem + nxt + ALO, va, tid);
            stsB<NO>(smem + nxt + BHO, smem + nxt + BLO, vb, tid);
        }
        if (kb + 2 < NKB) {                 // prefetch stage kb+2 into regs
            ldgA<KD>(va, A, bm0, kb + 2, tid);
            ldgB<KD, NO>(vb, Wsel, kb + 2, tid);
        }
        computeStage<NT>(sb + cur + AHO, sb + cur + ALO, sb + cur + BHO, sb + cur + BLO,
                         acc, wid, lane);
        __syncthreads();
    }

    // epilogue: bias + leaky + store + stats
    const int mbase = (wid >> 2) * 64;
    const int wn = (wid & 3) * (NT * 8);
    float csum[NT][2], csq[NT][2];
#pragma unroll
    for (int nt = 0; nt < NT; nt++) { csum[nt][0] = csum[nt][1] = 0.f; csq[nt][0] = csq[nt][1] = 0.f; }

#pragma unroll
    for (int mt = 0; mt < 4; mt++) {
        int r0 = bm0 + mbase + mt * 16 + (lane >> 2);
        int r1 = r0 + 8;
#pragma unroll
        for (int nt = 0; nt < NT; nt++) {
            int jl = wn + nt * 8 + (lane & 3) * 2;
            float b0 = s_bias[jl], b1 = s_bias[jl + 1];
            float x0 = acc[mt][nt][0] + b0; x0 = x0 > 0.f ? x0 : SLOPE * x0;
            float x1 = acc[mt][nt][1] + b1; x1 = x1 > 0.f ? x1 : SLOPE * x1;
            float x2 = acc[mt][nt][2] + b0; x2 = x2 > 0.f ? x2 : SLOPE * x2;
            float x3 = acc[mt][nt][3] + b1; x3 = x3 > 0.f ? x3 : SLOPE * x3;
            if (r0 < NROWS) {
                *(float2*)(Y + (size_t)r0 * NO + jl) = make_float2(x0, x1);
                csum[nt][0] += x0; csum[nt][1] += x1;
                csq[nt][0] += x0 * x0; csq[nt][1] += x1 * x1;
            }
            if (r1 < NROWS) {
                *(float2*)(Y + (size_t)r1 * NO + jl) = make_float2(x2, x3);
                csum[nt][0] += x2; csum[nt][1] += x3;
                csq[nt][0] += x2 * x2; csq[nt][1] += x3 * x3;
            }
        }
    }
#pragma unroll
    for (int nt = 0; nt < NT; nt++)
#pragma unroll
        for (int p = 0; p < 2; p++) {
            float s = csum[nt][p], q = csq[nt][p];
            s += __shfl_xor_sync(0xFFFFFFFFu, s, 4);  q += __shfl_xor_sync(0xFFFFFFFFu, q, 4);
            s += __shfl_xor_sync(0xFFFFFFFFu, s, 8);  q += __shfl_xor_sync(0xFFFFFFFFu, q, 8);
            s += __shfl_xor_sync(0xFFFFFFFFu, s, 16); q += __shfl_xor_sync(0xFFFFFFFFu, q, 16);
            if (lane < 4) {
                int col = wn + nt * 8 + lane * 2 + p;
                atomicAdd(&s_sum[col], s);
                atomicAdd(&s_sq[col], q);
            }
        }
    __syncthreads();
    if (tid < NO) {
        atomicAdd(gsum + tid, s_sum[tid]);
        atomicAdd(gsq + tid, s_sq[tid]);
    }
}

// ---------------- small kernels --------------------------------------------------
__global__ void zero_stats_kernel() {
    int t = threadIdx.x;  // 256
    g_sum1[t] = 0.f; g_sq1[t] = 0.f;
    g_sum2[t] = 0.f; g_sq2[t] = 0.f;
    if (t < DOUT) { g_sum3[t] = 0.f; g_sq3[t] = 0.f; }
}

__global__ void fold_kernel(const float* __restrict__ W, const float* __restrict__ b,
                            const float* __restrict__ g, const float* __restrict__ beta,
                            int layer) {
    int j = threadIdx.x;   // 256 = DH
    int o = blockIdx.x;
    const float* sum = (layer == 1) ? g_sum1 : g_sum2;
    const float* sq  = (layer == 1) ? g_sq1  : g_sq2;
    float* We        = (layer == 1) ? g_W2e  : g_W3e;
    float* be        = (layer == 1) ? g_b2e  : g_b3e;

    const float invN = 1.0f / (float)NROWS;
    float mean = sum[j] * invN;
    float var  = sq[j] * invN - mean * mean;
    float a = g[j] * rsqrtf(var + EPSBN);
    float c = beta[j] - mean * a;
    float w = W[o * DH + j];
    We[o * DH + j] = w * a;

    __shared__ float red[DH];
    red[j] = w * c;
    __syncthreads();
    for (int s = DH / 2; s > 0; s >>= 1) {
        if (j < s) red[j] += red[j + s];
        __syncthreads();
    }
    if (j == 0) be[o] = b[o] + red[0];
}

__global__ void prep3_kernel(const float* __restrict__ g, const float* __restrict__ beta) {
    int j = threadIdx.x;  // 128
    const float invN = 1.0f / (float)NROWS;
    float mean = g_sum3[j] * invN;
    float var  = g_sq3[j] * invN - mean * mean;
    float a = g[j] * rsqrtf(var + EPSBN);
    g_a3[j] = a;
    g_c3[j] = beta[j] - mean * a;
}

// fused: f = y3*a+c, node_update = affine(mean of neighbor y3).
// y3 = g_y1 referenced from DEVICE scope (host cannot take a __device__ var's
// address — that was the R3/R4/R12 bug).  Outputs go to d_out regions: no race.
__global__ void gather_affine_kernel(const int* __restrict__ nidx,
                                     float* __restrict__ fout,
                                     float* __restrict__ out) {
    __shared__ int sidx[2 * KNEI];
    int tid = threadIdx.x;              // 256 threads = 2 nodes
    int node0 = blockIdx.x * 2;
    if (tid < 2 * KNEI) sidx[tid] = nidx[(size_t)node0 * KNEI + tid];
    __syncthreads();
    int local = tid >> 7;
    int j = tid & (DOUT - 1);
    int node = node0 + local;
    float a = g_a3[j], c = g_c3[j];
    const float* y3 = g_y1;             // device-scope reference (valid)

    fout[(size_t)node * DOUT + j] = y3[(size_t)node * DOUT + j] * a + c;

    float s = 0.f;
#pragma unroll
    for (int k = 0; k < KNEI; k++) {
        int nk = sidx[local * KNEI + k];
        s += __ldg(y3 + (size_t)nk * DOUT + j);
    }
    out[(size_t)node * DOUT + j] = (s * (1.0f / KNEI)) * a + c;
}

// ---------------------------------------------------------------------------------
extern "C" void kernel_launch(void* const* d_in, const int* in_sizes, int n_in,
                              void* d_out, int out_size) {
    const float* X   = (const float*)d_in[0];
    const int*   nid = (const int*)d_in[1];
    const float* W1  = (const float*)d_in[3];
    const float* b1  = (const float*)d_in[4];
    const float* g1  = (const float*)d_in[5];
    const float* be1 = (const float*)d_in[6];
    const float* W2  = (const float*)d_in[7];
    const float* b2  = (const float*)d_in[8];
    const float* g2  = (const float*)d_in[9];
    const float* be2 = (const float*)d_in[10];
    const float* W3  = (const float*)d_in[11];
    const float* b3  = (const float*)d_in[12];
    const float* g3  = (const float*)d_in[13];
    const float* be3 = (const float*)d_in[14];

    float* out  = (float*)d_out;                   // node_update [N, DOUT]
    float* fbuf = out + (size_t)NROWS * DOUT;      // f           [N, DOUT]

    const int mblocks = (NROWS + 127) / 128;       // 782
    const int SM256 = 2 * (20480 + 2 * 256 * ARS) + 3 * 256 * 4;   // 125952
    const int SM128 = 2 * (20480 + 2 * 128 * ARS) + 3 * 128 * 4;   // 83456

    cudaFuncSetAttribute(gemm_mma3<128, 256, 0>, cudaFuncAttributeMaxDynamicSharedMemorySize, SM256);
    cudaFuncSetAttribute(gemm_mma3<256, 256, 1>, cudaFuncAttributeMaxDynamicSharedMemorySize, SM256);
    cudaFuncSetAttribute(gemm_mma3<256, 128, 2>, cudaFuncAttributeMaxDynamicSharedMemorySize, SM128);

    zero_stats_kernel<<<1, 256>>>();

    // layer 1: X @ W1^T -> g_y1 (+stats1).  W1 passed via 3rd arg (unused as output in MODE 0)
    gemm_mma3<128, 256, 0><<<mblocks, 256, SM256>>>(X, b1, (float*)W1);
    fold_kernel<<<DH, DH>>>(W2, b2, g1, be1, 1);
    gemm_mma3<256, 256, 1><<<mblocks, 256, SM256>>>(nullptr, nullptr, nullptr);
    fold_kernel<<<DOUT, DH>>>(W3, b3, g2, be2, 2);
    // layer 3: g_y2 @ W3e^T -> g_y1 scratch (raw y3, +stats3)
    gemm_mma3<256, 128, 2><<<mblocks, 256, SM128>>>(nullptr, nullptr, nullptr);

    prep3_kernel<<<1, DOUT>>>(g3, be3);
    // fused BN3 affine + neighbor-mean gather (reads g_y1 device-side)
    gather_affine_kernel<<<NROWS / 2, 256>>>(nid, fbuf, out);
}